// round 3
// baseline (speedup 1.0000x reference)
#include <cuda_runtime.h>

#define NB     16
#define SEQ    512
#define DMODEL 512
#define NFILT  512
#define MAXF   2048

// ---------------- scratch (static __device__ arrays: allowed) ----------------
__device__ float g_Hexp[NB * MAXF * DMODEL];   // 64 MB
__device__ float g_y1  [NB * MAXF * NFILT];    // 64 MB (reused by all 3 predictors)
__device__ float g_Wt  [6][3 * 512 * 512];     // transposed weights [k][c][f]
__device__ float g_part[NB * MAXF * 4];        // per-fblock partial dots
__device__ int   g_idx [NB * MAXF];            // expand indices (-1 = invalid)

// ---------------- weight transpose: w[f][c][k] -> Wt[k][c][f] ----------------
__global__ void wtrans_kernel(const float* __restrict__ w, int widx) {
    int kc = blockIdx.x;            // 0..1535 = c*3 + k
    int c  = kc / 3;
    int k  = kc - c * 3;
    int f  = threadIdx.x;           // 0..511 (coalesced writes)
    g_Wt[widx][(k * 512 + c) * 512 + f] = w[(f * 512 + c) * 3 + k];
}

// ---------------- duration cumsum + searchsorted ----------------
__global__ void duration_idx_kernel(const int* __restrict__ Dgt) {
    __shared__ int cs[512];
    int b = blockIdx.x, tid = threadIdx.x;
    int v = Dgt[b * 512 + tid];
    cs[tid] = v > 0 ? v : 0;
    __syncthreads();
    // inclusive Hillis-Steele scan
    for (int off = 1; off < 512; off <<= 1) {
        int add = (tid >= off) ? cs[tid - off] : 0;
        __syncthreads();
        cs[tid] += add;
        __syncthreads();
    }
    int total = cs[511];
    int Tmax  = total < MAXF ? total : MAXF;
    for (int t = tid; t < MAXF; t += 512) {
        int r;
        if (t >= Tmax) {
            r = -1;
        } else {
            int lo = 0, hi = 511;            // first i with cs[i] > t
            while (lo < hi) {
                int mid = (lo + hi) >> 1;
                if (cs[mid] > t) hi = mid; else lo = mid + 1;
            }
            r = lo;
        }
        g_idx[b * MAXF + t] = r;
    }
}

// ---------------- gather H_exp + fused variance adapt (writes d_out H_adapted) ----------------
__global__ void gather_adapt_kernel(const float* __restrict__ H,
                                    const float* __restrict__ P,
                                    const float* __restrict__ E,
                                    const float* __restrict__ pw,
                                    const float* __restrict__ pb,
                                    const float* __restrict__ ew,
                                    const float* __restrict__ eb,
                                    float* __restrict__ outH) {
    int bt  = blockIdx.x;           // b*2048 + t
    int b   = bt >> 11;
    int idx = g_idx[bt];
    int d   = threadIdx.x * 4;
    float4 h = make_float4(0.f, 0.f, 0.f, 0.f);
    if (idx >= 0) h = *(const float4*)&H[((long)(b * 512 + idx)) * 512 + d];
    *(float4*)&g_Hexp[(long)bt * 512 + d] = h;
    float p = P[bt], e = E[bt];
    float4 pw4 = *(const float4*)&pw[d];
    float4 pb4 = *(const float4*)&pb[d];
    float4 ew4 = *(const float4*)&ew[d];
    float4 eb4 = *(const float4*)&eb[d];
    float4 o;
    o.x = h.x + p * pw4.x + pb4.x + e * ew4.x + eb4.x;
    o.y = h.y + p * pw4.y + pb4.y + e * ew4.y + eb4.y;
    o.z = h.z + p * pw4.z + pb4.z + e * ew4.z + eb4.z;
    o.w = h.w + p * pw4.w + pb4.w + e * ew4.w + eb4.w;
    *(float4*)&outH[(long)bt * 512 + d] = o;
}

// ---------------- implicit-GEMM conv1d (K=3, C=512, F=512) ----------------
// Tile: 128 rows x 128 filters, BK=16, 256 threads, 8x8 register tile/thread.
// Thread columns split as [tx*4 .. tx*4+3] and [64+tx*4 .. 64+tx*4+3] to keep
// W smem reads at <=2-way conflict. A stored transposed [c][row] (stride 132,
// float4-aligned; 130-row halo) so per-c row reads are 3x LDS.128 broadcasts.
// FUSED=0: out = relu(conv + bias) -> g_y1
// FUSED=1: partial[row][fblk] = sum_f relu(conv + bias)*wl[f] -> g_part
template <int FUSED>
__global__ __launch_bounds__(256, 2)
void conv3_kernel(const float* __restrict__ Xext, int xsel, int widx, int S,
                  const float* __restrict__ bias, const float* __restrict__ wl) {
    __shared__ float sm[16 * 132 + 3 * 16 * 128];   // Ash 2112 | Wsh 6144 floats
    float* Ash = sm;
    float* Wsh = sm + 16 * 132;

    const float* X = (xsel == 0) ? Xext : (xsel == 1 ? g_Hexp : g_y1);
    const float* W = g_Wt[widx];

    const int tid = threadIdx.x;
    const int tx  = tid & 15;
    const int ty  = tid >> 4;
    const int ty8 = ty * 8;
    const int tx4 = tx * 4;

    const int rowBase = blockIdx.y * 128;
    const int b  = rowBase / S;
    const int s0 = rowBase - b * S;
    const int fBase = blockIdx.x * 128;

    float acc[8][8];
#pragma unroll
    for (int i = 0; i < 8; i++)
#pragma unroll
        for (int j = 0; j < 8; j++) acc[i][j] = 0.f;

    for (int c0 = 0; c0 < 512; c0 += 16) {
        // stage A: 130 rows (incl. +/-1 halo) x 16 channels, transposed into smem
#pragma unroll
        for (int it = 0; it < 3; ++it) {
            int i = tid + it * 256;
            if (i < 520) {
                int r = i >> 2, cg = i & 3;
                int s = s0 - 1 + r;
                float4 v = make_float4(0.f, 0.f, 0.f, 0.f);
                if (s >= 0 && s < S)
                    v = *(const float4*)(X + ((long)(b * S + s)) * 512 + c0 + cg * 4);
                int cb = cg * 4;
                Ash[(cb + 0) * 132 + r] = v.x;
                Ash[(cb + 1) * 132 + r] = v.y;
                Ash[(cb + 2) * 132 + r] = v.z;
                Ash[(cb + 3) * 132 + r] = v.w;
            }
        }
        // stage W: 3 taps x 16 channels x 128 filters (coalesced)
#pragma unroll
        for (int it = 0; it < 6; ++it) {
            int i  = tid + it * 256;       // 0..1535
            int f4 = i & 31;
            int kc = i >> 5;
            int k  = kc >> 4, cc = kc & 15;
            float4 v = *(const float4*)(W + (k * 512 + c0 + cc) * 512 + fBase + f4 * 4);
            *(float4*)&Wsh[(k * 16 + cc) * 128 + f4 * 4] = v;
        }
        __syncthreads();

#pragma unroll 2
        for (int cc = 0; cc < 16; ++cc) {
            float a[12];
            {
                float4 a0 = *(const float4*)&Ash[cc * 132 + ty8];
                float4 a1 = *(const float4*)&Ash[cc * 132 + ty8 + 4];
                float4 a2 = *(const float4*)&Ash[cc * 132 + ty8 + 8];
                a[0] = a0.x; a[1] = a0.y; a[2] = a0.z; a[3] = a0.w;
                a[4] = a1.x; a[5] = a1.y; a[6] = a1.z; a[7] = a1.w;
                a[8] = a2.x; a[9] = a2.y; a[10] = a2.z; a[11] = a2.w;
            }
            float w[3][8];
#pragma unroll
            for (int k = 0; k < 3; k++) {
                float4 wA = *(const float4*)&Wsh[(k * 16 + cc) * 128 + tx4];
                float4 wB = *(const float4*)&Wsh[(k * 16 + cc) * 128 + tx4 + 64];
                w[k][0] = wA.x; w[k][1] = wA.y; w[k][2] = wA.z; w[k][3] = wA.w;
                w[k][4] = wB.x; w[k][5] = wB.y; w[k][6] = wB.z; w[k][7] = wB.w;
            }
#pragma unroll
            for (int i = 0; i < 8; i++) {
#pragma unroll
                for (int k = 0; k < 3; k++) {
                    float av = a[i + k];
#pragma unroll
                    for (int j = 0; j < 8; j++) acc[i][j] += av * w[k][j];
                }
            }
        }
        __syncthreads();
    }

    const int cA = fBase + tx4;
    const int cB = cA + 64;
    float4 bA = *(const float4*)&bias[cA];
    float4 bB = *(const float4*)&bias[cB];

    if (FUSED == 0) {
#pragma unroll
        for (int i = 0; i < 8; i++) {
            long row = rowBase + ty8 + i;
            float4 oA, oB;
            oA.x = fmaxf(acc[i][0] + bA.x, 0.f);
            oA.y = fmaxf(acc[i][1] + bA.y, 0.f);
            oA.z = fmaxf(acc[i][2] + bA.z, 0.f);
            oA.w = fmaxf(acc[i][3] + bA.w, 0.f);
            oB.x = fmaxf(acc[i][4] + bB.x, 0.f);
            oB.y = fmaxf(acc[i][5] + bB.y, 0.f);
            oB.z = fmaxf(acc[i][6] + bB.z, 0.f);
            oB.w = fmaxf(acc[i][7] + bB.w, 0.f);
            *(float4*)&g_y1[row * 512 + cA] = oA;
            *(float4*)&g_y1[row * 512 + cB] = oB;
        }
    } else {
        float4 wA = *(const float4*)&wl[cA];
        float4 wB = *(const float4*)&wl[cB];
        float p[8];
#pragma unroll
        for (int i = 0; i < 8; i++) {
            float s = 0.f;
            s += fmaxf(acc[i][0] + bA.x, 0.f) * wA.x;
            s += fmaxf(acc[i][1] + bA.y, 0.f) * wA.y;
            s += fmaxf(acc[i][2] + bA.z, 0.f) * wA.z;
            s += fmaxf(acc[i][3] + bA.w, 0.f) * wA.w;
            s += fmaxf(acc[i][4] + bB.x, 0.f) * wB.x;
            s += fmaxf(acc[i][5] + bB.y, 0.f) * wB.y;
            s += fmaxf(acc[i][6] + bB.z, 0.f) * wB.z;
            s += fmaxf(acc[i][7] + bB.w, 0.f) * wB.w;
            p[i] = s;
        }
        // cross-tx reduce through smem (deterministic, no float atomics)
        float* red = sm;   // safe to reuse: last loop iteration ended in __syncthreads
#pragma unroll
        for (int i = 0; i < 8; i++) red[(ty8 + i) * 17 + tx] = p[i];
        __syncthreads();
        if (tid < 128) {
            float s = 0.f;
#pragma unroll
            for (int x = 0; x < 16; x++) s += red[tid * 17 + x];
            g_part[(long)(rowBase + tid) * 4 + blockIdx.x] = s;
        }
    }
}

// ---------------- final pred reduce: out = bl + sum of 4 fblock partials ----------------
__global__ void pred_reduce_kernel(const float* __restrict__ bl,
                                   float* __restrict__ out, int rows) {
    int i = blockIdx.x * 256 + threadIdx.x;
    if (i < rows)
        out[i] = bl[0] + g_part[i * 4 + 0] + g_part[i * 4 + 1] +
                 g_part[i * 4 + 2] + g_part[i * 4 + 3];
}

// ---------------- launch ----------------
extern "C" void kernel_launch(void* const* d_in, const int* in_sizes, int n_in,
                              void* d_out, int out_size) {
    const float* H     = (const float*)d_in[0];
    const int*   Dgt   = (const int*)  d_in[1];
    const float* Pgt   = (const float*)d_in[2];
    const float* Egt   = (const float*)d_in[3];
    const float* dp_w1 = (const float*)d_in[4];
    const float* dp_b1 = (const float*)d_in[5];
    const float* dp_w2 = (const float*)d_in[6];
    const float* dp_b2 = (const float*)d_in[7];
    const float* dp_wl = (const float*)d_in[8];
    const float* dp_bl = (const float*)d_in[9];
    const float* pp_w1 = (const float*)d_in[10];
    const float* pp_b1 = (const float*)d_in[11];
    const float* pp_w2 = (const float*)d_in[12];
    const float* pp_b2 = (const float*)d_in[13];
    const float* pp_wl = (const float*)d_in[14];
    const float* pp_bl = (const float*)d_in[15];
    const float* ep_w1 = (const float*)d_in[16];
    const float* ep_b1 = (const float*)d_in[17];
    const float* ep_w2 = (const float*)d_in[18];
    const float* ep_b2 = (const float*)d_in[19];
    const float* ep_wl = (const float*)d_in[20];
    const float* ep_bl = (const float*)d_in[21];
    const float* pw    = (const float*)d_in[22];
    const float* pb    = (const float*)d_in[23];
    const float* ew    = (const float*)d_in[24];
    const float* eb    = (const float*)d_in[25];

    float* out  = (float*)d_out;
    float* outH = out;                                   // (16,2048,512)
    float* outD = out + (long)NB * MAXF * DMODEL;        // (16,512)
    float* outP = outD + NB * SEQ;                       // (16,2048)
    float* outE = outP + NB * MAXF;                      // (16,2048)

    // weight transposes (tiny)
    wtrans_kernel<<<1536, 512>>>(dp_w1, 0);
    wtrans_kernel<<<1536, 512>>>(dp_w2, 1);
    wtrans_kernel<<<1536, 512>>>(pp_w1, 2);
    wtrans_kernel<<<1536, 512>>>(pp_w2, 3);
    wtrans_kernel<<<1536, 512>>>(ep_w1, 4);
    wtrans_kernel<<<1536, 512>>>(ep_w2, 5);

    // expand + adapt
    duration_idx_kernel<<<NB, 512>>>(Dgt);
    gather_adapt_kernel<<<NB * MAXF, 128>>>(H, Pgt, Egt, pw, pb, ew, eb, outH);

    // duration predictor (on H, S=512)
    conv3_kernel<0><<<dim3(4, 64), 256>>>(H, 0, 0, SEQ, dp_b1, nullptr);
    conv3_kernel<1><<<dim3(4, 64), 256>>>(nullptr, 2, 1, SEQ, dp_b2, dp_wl);
    pred_reduce_kernel<<<32, 256>>>(dp_bl, outD, NB * SEQ);

    // pitch predictor (on H_exp, S=2048)
    conv3_kernel<0><<<dim3(4, 256), 256>>>(nullptr, 1, 2, MAXF, pp_b1, nullptr);
    conv3_kernel<1><<<dim3(4, 256), 256>>>(nullptr, 2, 3, MAXF, pp_b2, pp_wl);
    pred_reduce_kernel<<<128, 256>>>(pp_bl, outP, NB * MAXF);

    // energy predictor (on H_exp, S=2048)
    conv3_kernel<0><<<dim3(4, 256), 256>>>(nullptr, 1, 4, MAXF, ep_b1, nullptr);
    conv3_kernel<1><<<dim3(4, 256), 256>>>(nullptr, 2, 5, MAXF, ep_b2, ep_wl);
    pred_reduce_kernel<<<128, 256>>>(ep_bl, outE, NB * MAXF);
}

// round 6
// speedup vs baseline: 1.6093x; 1.6093x over previous
#include <cuda_runtime.h>
#include <cuda_bf16.h>
#include <cstdint>

#define NB     16
#define SEQ    512
#define DMODEL 512
#define MAXF   2048

// ---------------- scratch (static __device__ arrays: allowed) ----------------
// A operands pre-split to bf16 hi/lo. X: conv-1 inputs (H, then Hexp). Y: relu(conv1) outputs.
__device__ __align__(128) __nv_bfloat16 g_Xhi[NB * MAXF * DMODEL];
__device__ __align__(128) __nv_bfloat16 g_Xlo[NB * MAXF * DMODEL];
__device__ __align__(128) __nv_bfloat16 g_Yhi[NB * MAXF * DMODEL];
__device__ __align__(128) __nv_bfloat16 g_Ylo[NB * MAXF * DMODEL];
__device__ __align__(128) __nv_bfloat16 g_Whi[6 * 3 * 512 * 512];   // [conv][tap][f][c]
__device__ __align__(128) __nv_bfloat16 g_Wlo[6 * 3 * 512 * 512];
__device__ float g_part[NB * MAXF * 4];                             // per f-tile partial dots
__device__ int   g_idx [NB * MAXF];                                 // expand indices (-1 = invalid)

// ================= baseline-ISA helpers (compute_103-safe; NO tcgen05) =================
__device__ __forceinline__ uint32_t smem_to_u32(const void* p) {
    uint32_t a;
    asm("{ .reg .u64 t; cvta.to.shared.u64 t, %1; cvt.u32.u64 %0, t; }" : "=r"(a) : "l"(p));
    return a;
}
__device__ __forceinline__ void cpasync16(uint32_t dst, const void* src, bool pred) {
    int sz = pred ? 16 : 0;
    asm volatile("cp.async.cg.shared.global [%0], [%1], 16, %2;"
                 :: "r"(dst), "l"(src), "r"(sz));
}
#define CP_COMMIT() asm volatile("cp.async.commit_group;" ::: "memory")
#define CP_WAIT1()  asm volatile("cp.async.wait_group 1;"  ::: "memory")

__device__ __forceinline__ void ldmx4(uint32_t* r, uint32_t addr) {
    asm volatile("ldmatrix.sync.aligned.m8n8.x4.shared.b16 {%0,%1,%2,%3}, [%4];"
                 : "=r"(r[0]), "=r"(r[1]), "=r"(r[2]), "=r"(r[3]) : "r"(addr));
}
__device__ __forceinline__ void mma16816(float* d, const uint32_t* a, const uint32_t* b) {
    asm volatile("mma.sync.aligned.m16n8k16.row.col.f32.bf16.bf16.f32 "
                 "{%0,%1,%2,%3}, {%4,%5,%6,%7}, {%8,%9}, {%0,%1,%2,%3};"
                 : "+f"(d[0]), "+f"(d[1]), "+f"(d[2]), "+f"(d[3])
                 : "r"(a[0]), "r"(a[1]), "r"(a[2]), "r"(a[3]), "r"(b[0]), "r"(b[1]));
}

__device__ __forceinline__ uint32_t pack2bf(float a, float b) {
    __nv_bfloat162 t = __floats2bfloat162_rn(a, b);
    return *reinterpret_cast<uint32_t*>(&t);
}

// ---------------- weight transpose + hi/lo split: w[f][c][k] -> W*[conv][tap][f][c] ----------------
__global__ void wsplit_kernel(const float* __restrict__ w, int conv) {
    int tf  = blockIdx.x;            // 0..1535 = tap*512 + f
    int tap = tf >> 9;
    int f   = tf & 511;
    int c   = threadIdx.x;           // 0..511
    float v = w[(f * 512 + c) * 3 + tap];
    __nv_bfloat16 h = __float2bfloat16(v);
    float rem = v - __bfloat162float(h);
    long o = ((long)(conv * 3 + tap) * 512 + f) * 512 + c;
    g_Whi[o] = h;
    g_Wlo[o] = __float2bfloat16(rem);
}

// ---------------- split H (fp32) -> g_Xhi/g_Xlo ----------------
__global__ void hsplit_kernel(const float* __restrict__ H) {
    long i = (long)blockIdx.x * 512 + threadIdx.x * 4;   // gridDim = NB*SEQ, 128 thr
    float4 v = *(const float4*)&H[i];
    float vv[4] = {v.x, v.y, v.z, v.w};
    float hh[4];
#pragma unroll
    for (int k = 0; k < 4; k++) hh[k] = __bfloat162float(__float2bfloat16(vv[k]));
    *(uint32_t*)&g_Xhi[i]     = pack2bf(hh[0], hh[1]);
    *(uint32_t*)&g_Xhi[i + 2] = pack2bf(hh[2], hh[3]);
    *(uint32_t*)&g_Xlo[i]     = pack2bf(vv[0] - hh[0], vv[1] - hh[1]);
    *(uint32_t*)&g_Xlo[i + 2] = pack2bf(vv[2] - hh[2], vv[3] - hh[3]);
}

// ---------------- duration cumsum + searchsorted ----------------
__global__ void duration_idx_kernel(const int* __restrict__ Dgt) {
    __shared__ int cs[512];
    int b = blockIdx.x, tid = threadIdx.x;
    int v = Dgt[b * 512 + tid];
    cs[tid] = v > 0 ? v : 0;
    __syncthreads();
    for (int off = 1; off < 512; off <<= 1) {
        int add = (tid >= off) ? cs[tid - off] : 0;
        __syncthreads();
        cs[tid] += add;
        __syncthreads();
    }
    int total = cs[511];
    int Tmax  = total < MAXF ? total : MAXF;
    for (int t = tid; t < MAXF; t += 512) {
        int r;
        if (t >= Tmax) {
            r = -1;
        } else {
            int lo = 0, hi = 511;
            while (lo < hi) {
                int mid = (lo + hi) >> 1;
                if (cs[mid] > t) hi = mid; else lo = mid + 1;
            }
            r = lo;
        }
        g_idx[b * MAXF + t] = r;
    }
}

// ---------------- gather H_exp (split to g_X) + fused variance adapt (fp32 to d_out) ----------------
__global__ void gather_adapt_kernel(const float* __restrict__ H,
                                    const float* __restrict__ P,
                                    const float* __restrict__ E,
                                    const float* __restrict__ pw,
                                    const float* __restrict__ pb,
                                    const float* __restrict__ ew,
                                    const float* __restrict__ eb,
                                    float* __restrict__ outH) {
    int bt  = blockIdx.x;
    int b   = bt >> 11;
    int idx = g_idx[bt];
    int d   = threadIdx.x * 4;
    float4 h = make_float4(0.f, 0.f, 0.f, 0.f);
    if (idx >= 0) h = *(const float4*)&H[((long)(b * 512 + idx)) * 512 + d];

    long xo = (long)bt * 512 + d;
    float vv[4] = {h.x, h.y, h.z, h.w};
    float hh[4];
#pragma unroll
    for (int k = 0; k < 4; k++) hh[k] = __bfloat162float(__float2bfloat16(vv[k]));
    *(uint32_t*)&g_Xhi[xo]     = pack2bf(hh[0], hh[1]);
    *(uint32_t*)&g_Xhi[xo + 2] = pack2bf(hh[2], hh[3]);
    *(uint32_t*)&g_Xlo[xo]     = pack2bf(vv[0] - hh[0], vv[1] - hh[1]);
    *(uint32_t*)&g_Xlo[xo + 2] = pack2bf(vv[2] - hh[2], vv[3] - hh[3]);

    float p = P[bt], e = E[bt];
    float4 pw4 = *(const float4*)&pw[d];
    float4 pb4 = *(const float4*)&pb[d];
    float4 ew4 = *(const float4*)&ew[d];
    float4 eb4 = *(const float4*)&eb[d];
    float4 o;
    o.x = h.x + p * pw4.x + pb4.x + e * ew4.x + eb4.x;
    o.y = h.y + p * pw4.y + pb4.y + e * ew4.y + eb4.y;
    o.z = h.z + p * pw4.z + pb4.z + e * ew4.z + eb4.z;
    o.w = h.w + p * pw4.w + pb4.w + e * ew4.w + eb4.w;
    *(float4*)&outH[xo] = o;
}

// ---------------- tensor-core conv1d via mma.sync (K=3, C=512, F=512), 3xBF16 compensated ----------------
// CTA tile: 128 rows x 128 filters. 8 warps (warp tile 32x64). K-chunks of 64 ch,
// 24 chunks (8 per tap x 3 taps), cp.async double-buffered, XOR-swizzled smem.
// FUSED=0: g_Yhi/g_Ylo[row][f] = split(relu(conv + bias))
// FUSED=1: g_part[row*4 + ftile] = sum_f relu(conv + bias) * wl[f]
#define SMEM_BUF 65536   // Ahi 16K | Alo 16K | Bhi 16K | Blo 16K

template <int FUSED>
__global__ __launch_bounds__(256, 1)
void conv_mma_kernel(int xsel, int conv, int S,
                     const float* __restrict__ bias, const float* __restrict__ wl) {
    extern __shared__ char sm[];
    const uint32_t sb = smem_to_u32(sm);
    __shared__ float s_bias[128];
    __shared__ float s_wl[128];
    __shared__ float s_part[128][2];

    const int tid  = threadIdx.x;
    const int lane = tid & 31;
    const int wid  = tid >> 5;
    const int warpM = wid & 3, warpN = wid >> 2;
    const int rowW = warpM * 32, colW = warpN * 64;

    const int rowBase = blockIdx.y * 128;
    const int fBase   = blockIdx.x * 128;
    const int bb = rowBase / S;
    const int s0 = rowBase - bb * S;

    const __nv_bfloat16* Xhi = (xsel == 0 ? g_Xhi : g_Yhi) + (long)bb * S * 512;
    const __nv_bfloat16* Xlo = (xsel == 0 ? g_Xlo : g_Ylo) + (long)bb * S * 512;
    const __nv_bfloat16* WhC = g_Whi + ((long)(conv * 3) * 512 + fBase) * 512;
    const __nv_bfloat16* WlC = g_Wlo + ((long)(conv * 3) * 512 + fBase) * 512;

    if (tid < 128) {
        s_bias[tid] = bias[fBase + tid];
        if (FUSED) s_wl[tid] = wl[fBase + tid];
    }

    // ---- staging lambda: chunk kc -> buffer ----
    auto stage = [&](int kc, uint32_t buf) {
        const int tap = kc >> 3;
        const int c0  = (kc & 7) << 6;
        const int sr0 = s0 + tap - 1;
        const __nv_bfloat16* Wh = WhC + (long)tap * 512 * 512 + c0;
        const __nv_bfloat16* Wl = WlC + (long)tap * 512 * 512 + c0;
#pragma unroll
        for (int q = 0; q < 4; q++) {
            int idx = tid + q * 256;       // 0..1023
            int r   = idx >> 3;
            int c16 = idx & 7;
            // A rows
            int s = sr0 + r;
            bool p = (s >= 0 && s < S);
            int sc = p ? s : 0;
            const __nv_bfloat16* srcA = Xhi + (long)sc * 512 + c0 + c16 * 8;
            const __nv_bfloat16* srcAl = Xlo + (long)sc * 512 + c0 + c16 * 8;
            uint32_t dsw = (uint32_t)(r * 128 + ((c16 ^ (r & 7)) << 4));
            cpasync16(buf + dsw,          srcA,  p);
            cpasync16(buf + 16384 + dsw,  srcAl, p);
            // B rows (filter fr = r)
            const __nv_bfloat16* srcBh = Wh + (long)r * 512 + c16 * 8;
            const __nv_bfloat16* srcBl = Wl + (long)r * 512 + c16 * 8;
            cpasync16(buf + 32768 + dsw, srcBh, true);
            cpasync16(buf + 49152 + dsw, srcBl, true);
        }
    };

    // ---- per-lane ldmatrix address bases ----
    const int q = lane >> 3;
    int am[2], an[4];
#pragma unroll
    for (int mt = 0; mt < 2; mt++) am[mt] = rowW + mt * 16 + ((q & 1) << 3) + (lane & 7);
#pragma unroll
    for (int np = 0; np < 4; np++) an[np] = colW + np * 16 + ((q >> 1) << 3) + (lane & 7);
    const int ac16b = q >> 1;   // A: mats (m0k0, m8k0, m0k8, m8k8)
    const int bc16b = q & 1;    // B: mats (n0k0, n0k8, n8k0, n8k8)

    float acc[2][8][4];
#pragma unroll
    for (int mt = 0; mt < 2; mt++)
#pragma unroll
        for (int nt = 0; nt < 8; nt++)
#pragma unroll
            for (int v = 0; v < 4; v++) acc[mt][nt][v] = 0.f;

    stage(0, sb);            CP_COMMIT();
    stage(1, sb + SMEM_BUF); CP_COMMIT();

    for (int kc = 0; kc < 24; kc++) {
        CP_WAIT1();
        __syncthreads();
        const uint32_t buf = sb + (kc & 1) * SMEM_BUF;
        const uint32_t bufAh = buf, bufAl = buf + 16384;
        const uint32_t bufBh = buf + 32768, bufBl = buf + 49152;

#pragma unroll
        for (int ks = 0; ks < 4; ks++) {
            const int ks2 = ks * 2;
            uint32_t ah[2][4], al[2][4];
#pragma unroll
            for (int mt = 0; mt < 2; mt++) {
                uint32_t off = (uint32_t)(am[mt] * 128 + (((ks2 + ac16b) ^ (am[mt] & 7)) << 4));
                ldmx4(ah[mt], bufAh + off);
                ldmx4(al[mt], bufAl + off);
            }
            uint32_t bh[8][2], bl[8][2];
#pragma unroll
            for (int np = 0; np < 4; np++) {
                uint32_t off = (uint32_t)(an[np] * 128 + (((ks2 + bc16b) ^ (an[np] & 7)) << 4));
                uint32_t t[4];
                ldmx4(t, bufBh + off);
                bh[2 * np][0] = t[0]; bh[2 * np][1] = t[1];
                bh[2 * np + 1][0] = t[2]; bh[2 * np + 1][1] = t[3];
                ldmx4(t, bufBl + off);
                bl[2 * np][0] = t[0]; bl[2 * np][1] = t[1];
                bl[2 * np + 1][0] = t[2]; bl[2 * np + 1][1] = t[3];
            }
            // 3-term compensated accumulate; chain distance 16 between same-acc mmas
#pragma unroll
            for (int mt = 0; mt < 2; mt++)
#pragma unroll
                for (int nt = 0; nt < 8; nt++) mma16816(acc[mt][nt], ah[mt], bh[nt]);
#pragma unroll
            for (int mt = 0; mt < 2; mt++)
#pragma unroll
                for (int nt = 0; nt < 8; nt++) mma16816(acc[mt][nt], ah[mt], bl[nt]);
#pragma unroll
            for (int mt = 0; mt < 2; mt++)
#pragma unroll
                for (int nt = 0; nt < 8; nt++) mma16816(acc[mt][nt], al[mt], bh[nt]);
        }
        __syncthreads();
        if (kc + 2 < 24) stage(kc + 2, buf);
        CP_COMMIT();
    }

    // ---------------- epilogue ----------------
    const int tq = lane >> 2;          // fragment row within m16
    const int tr = lane & 3;           // fragment col pair
    if (FUSED == 0) {
#pragma unroll
        for (int mt = 0; mt < 2; mt++) {
            const long r0 = rowBase + rowW + mt * 16 + tq;
#pragma unroll
            for (int nt = 0; nt < 8; nt++) {
                const int cl = colW + nt * 8 + 2 * tr;
                const float b0 = s_bias[cl], b1 = s_bias[cl + 1];
#pragma unroll
                for (int h = 0; h < 2; h++) {      // h=0: row r0, h=1: row r0+8
                    const long row = r0 + h * 8;
                    float v0 = fmaxf(acc[mt][nt][2 * h]     + b0, 0.f);
                    float v1 = fmaxf(acc[mt][nt][2 * h + 1] + b1, 0.f);
                    float h0 = __bfloat162float(__float2bfloat16(v0));
                    float h1 = __bfloat162float(__float2bfloat16(v1));
                    long o = row * 512 + fBase + cl;
                    *(uint32_t*)&g_Yhi[o] = pack2bf(h0, h1);
                    *(uint32_t*)&g_Ylo[o] = pack2bf(v0 - h0, v1 - h1);
                }
            }
        }
    } else {
#pragma unroll
        for (int mt = 0; mt < 2; mt++) {
            float sum0 = 0.f, sum1 = 0.f;
#pragma unroll
            for (int nt = 0; nt < 8; nt++) {
                const int cl = colW + nt * 8 + 2 * tr;
                const float b0 = s_bias[cl], b1 = s_bias[cl + 1];
                const float w0 = s_wl[cl], w1 = s_wl[cl + 1];
                sum0 += fmaxf(acc[mt][nt][0] + b0, 0.f) * w0
                      + fmaxf(acc[mt][nt][1] + b1, 0.f) * w1;
                sum1 += fmaxf(acc[mt][nt][2] + b0, 0.f) * w0
                      + fmaxf(acc[mt][nt][3] + b1, 0.f) * w1;
            }
            sum0 += __shfl_xor_sync(0xFFFFFFFF, sum0, 1);
            sum0 += __shfl_xor_sync(0xFFFFFFFF, sum0, 2);
            sum1 += __shfl_xor_sync(0xFFFFFFFF, sum1, 1);
            sum1 += __shfl_xor_sync(0xFFFFFFFF, sum1, 2);
            if (tr == 0) {
                s_part[rowW + mt * 16 + tq][warpN]     = sum0;
                s_part[rowW + mt * 16 + tq + 8][warpN] = sum1;
            }
        }
        __syncthreads();
        if (tid < 128)
            g_part[(long)(rowBase + tid) * 4 + blockIdx.x] = s_part[tid][0] + s_part[tid][1];
    }
}

// ---------------- final pred reduce: out = bl + sum of 4 f-tile partials ----------------
__global__ void pred_reduce_kernel(const float* __restrict__ bl,
                                   float* __restrict__ out, int rows) {
    int i = blockIdx.x * 256 + threadIdx.x;
    if (i < rows)
        out[i] = bl[0] + g_part[(long)i * 4 + 0] + g_part[(long)i * 4 + 1] +
                 g_part[(long)i * 4 + 2] + g_part[(long)i * 4 + 3];
}

// ---------------- launch ----------------
extern "C" void kernel_launch(void* const* d_in, const int* in_sizes, int n_in,
                              void* d_out, int out_size) {
    const float* H     = (const float*)d_in[0];
    const int*   Dgt   = (const int*)  d_in[1];
    const float* Pgt   = (const float*)d_in[2];
    const float* Egt   = (const float*)d_in[3];
    const float* dp_w1 = (const float*)d_in[4];
    const float* dp_b1 = (const float*)d_in[5];
    const float* dp_w2 = (const float*)d_in[6];
    const float* dp_b2 = (const float*)d_in[7];
    const float* dp_wl = (const float*)d_in[8];
    const float* dp_bl = (const float*)d_in[9];
    const float* pp_w1 = (const float*)d_in[10];
    const float* pp_b1 = (const float*)d_in[11];
    const float* pp_w2 = (const float*)d_in[12];
    const float* pp_b2 = (const float*)d_in[13];
    const float* pp_wl = (const float*)d_in[14];
    const float* pp_bl = (const float*)d_in[15];
    const float* ep_w1 = (const float*)d_in[16];
    const float* ep_b1 = (const float*)d_in[17];
    const float* ep_w2 = (const float*)d_in[18];
    const float* ep_b2 = (const float*)d_in[19];
    const float* ep_wl = (const float*)d_in[20];
    const float* ep_bl = (const float*)d_in[21];
    const float* pw    = (const float*)d_in[22];
    const float* pb    = (const float*)d_in[23];
    const float* ew    = (const float*)d_in[24];
    const float* eb    = (const float*)d_in[25];

    float* out  = (float*)d_out;
    float* outH = out;                                   // (16,2048,512)
    float* outD = out + (long)NB * MAXF * DMODEL;        // (16,512)
    float* outP = outD + NB * SEQ;                       // (16,2048)
    float* outE = outP + NB * MAXF;                      // (16,2048)

    const int DSM = 2 * SMEM_BUF;                        // 131072 bytes
    cudaFuncSetAttribute(conv_mma_kernel<0>, cudaFuncAttributeMaxDynamicSharedMemorySize, DSM);
    cudaFuncSetAttribute(conv_mma_kernel<1>, cudaFuncAttributeMaxDynamicSharedMemorySize, DSM);

    // weight transpose + hi/lo split (tiny)
    wsplit_kernel<<<1536, 512>>>(dp_w1, 0);
    wsplit_kernel<<<1536, 512>>>(dp_w2, 1);
    wsplit_kernel<<<1536, 512>>>(pp_w1, 2);
    wsplit_kernel<<<1536, 512>>>(pp_w2, 3);
    wsplit_kernel<<<1536, 512>>>(ep_w1, 4);
    wsplit_kernel<<<1536, 512>>>(ep_w2, 5);

    duration_idx_kernel<<<NB, 512>>>(Dgt);

    // ---- duration predictor (input: split H; S=512) ----
    hsplit_kernel<<<NB * SEQ, 128>>>(H);
    conv_mma_kernel<0><<<dim3(4, 64), 256, DSM>>>(0, 0, SEQ, dp_b1, nullptr);
    conv_mma_kernel<1><<<dim3(4, 64), 256, DSM>>>(1, 1, SEQ, dp_b2, dp_wl);
    pred_reduce_kernel<<<32, 256>>>(dp_bl, outD, NB * SEQ);

    // ---- expand + adapt (overwrites g_X with split Hexp; writes outH fp32) ----
    gather_adapt_kernel<<<NB * MAXF, 128>>>(H, Pgt, Egt, pw, pb, ew, eb, outH);

    // ---- pitch predictor (input: split Hexp; S=2048) ----
    conv_mma_kernel<0><<<dim3(4, 256), 256, DSM>>>(0, 2, MAXF, pp_b1, nullptr);
    conv_mma_kernel<1><<<dim3(4, 256), 256, DSM>>>(1, 3, MAXF, pp_b2, pp_wl);
    pred_reduce_kernel<<<128, 256>>>(pp_bl, outP, NB * MAXF);

    // ---- energy predictor (input: split Hexp, still in g_X; S=2048) ----
    conv_mma_kernel<0><<<dim3(4, 256), 256, DSM>>>(0, 4, MAXF, ep_b1, nullptr);
    conv_mma_kernel<1><<<dim3(4, 256), 256, DSM>>>(1, 5, MAXF, ep_b2, ep_wl);
    pred_reduce_kernel<<<128, 256>>>(ep_bl, outE, NB * MAXF);
}

// round 7
// speedup vs baseline: 2.5499x; 1.5845x over previous
#include <cuda_runtime.h>
#include <cuda_bf16.h>
#include <cstdint>

#define NB     16
#define SEQ    512
#define DMODEL 512
#define MAXF   2048

// ---------------- scratch (static __device__ arrays: allowed) ----------------
__device__ __align__(128) __nv_bfloat16 g_Xhi[NB * MAXF * DMODEL];
__device__ __align__(128) __nv_bfloat16 g_Xlo[NB * MAXF * DMODEL];
__device__ __align__(128) __nv_bfloat16 g_Yhi[NB * MAXF * DMODEL];
__device__ __align__(128) __nv_bfloat16 g_Ylo[NB * MAXF * DMODEL];
__device__ __align__(128) __nv_bfloat16 g_Whi[6 * 3 * 512 * 512];   // [conv][tap][f][c]
__device__ __align__(128) __nv_bfloat16 g_Wlo[6 * 3 * 512 * 512];
__device__ float g_part[NB * MAXF * 4];
__device__ int   g_idx [NB * MAXF];

// ================= baseline-ISA helpers (compute_103-safe; NO tcgen05) =================
__device__ __forceinline__ uint32_t smem_to_u32(const void* p) {
    uint32_t a;
    asm("{ .reg .u64 t; cvta.to.shared.u64 t, %1; cvt.u32.u64 %0, t; }" : "=r"(a) : "l"(p));
    return a;
}
__device__ __forceinline__ void cpasync16(uint32_t dst, const void* src, bool pred) {
    int sz = pred ? 16 : 0;
    asm volatile("cp.async.cg.shared.global [%0], [%1], 16, %2;"
                 :: "r"(dst), "l"(src), "r"(sz));
}
#define CP_COMMIT() asm volatile("cp.async.commit_group;" ::: "memory")
#define CP_WAIT1()  asm volatile("cp.async.wait_group 1;"  ::: "memory")

__device__ __forceinline__ void ldmx4(uint32_t* r, uint32_t addr) {
    asm volatile("ldmatrix.sync.aligned.m8n8.x4.shared.b16 {%0,%1,%2,%3}, [%4];"
                 : "=r"(r[0]), "=r"(r[1]), "=r"(r[2]), "=r"(r[3]) : "r"(addr));
}
__device__ __forceinline__ void mma16816(float* d, const uint32_t* a, const uint32_t* b) {
    asm volatile("mma.sync.aligned.m16n8k16.row.col.f32.bf16.bf16.f32 "
                 "{%0,%1,%2,%3}, {%4,%5,%6,%7}, {%8,%9}, {%0,%1,%2,%3};"
                 : "+f"(d[0]), "+f"(d[1]), "+f"(d[2]), "+f"(d[3])
                 : "r"(a[0]), "r"(a[1]), "r"(a[2]), "r"(a[3]), "r"(b[0]), "r"(b[1]));
}
__device__ __forceinline__ uint32_t pack2bf(float a, float b) {
    __nv_bfloat162 t = __floats2bfloat162_rn(a, b);
    return *reinterpret_cast<uint32_t*>(&t);
}

// ---------------- weight transpose + hi/lo split: w[f][c][k] -> W*[conv][tap][f][c] ----------------
__global__ void wsplit_kernel(const float* __restrict__ w, int conv) {
    int tf  = blockIdx.x;            // 0..1535 = tap*512 + f
    int tap = tf >> 9;
    int f   = tf & 511;
    int c   = threadIdx.x;
    float v = w[(f * 512 + c) * 3 + tap];
    __nv_bfloat16 h = __float2bfloat16(v);
    float rem = v - __bfloat162float(h);
    long o = ((long)(conv * 3 + tap) * 512 + f) * 512 + c;
    g_Whi[o] = h;
    g_Wlo[o] = __float2bfloat16(rem);
}

// ---------------- split H (fp32) -> g_Xhi/g_Xlo ----------------
__global__ void hsplit_kernel(const float* __restrict__ H) {
    long i = (long)blockIdx.x * 512 + threadIdx.x * 4;
    float4 v = *(const float4*)&H[i];
    float vv[4] = {v.x, v.y, v.z, v.w};
    float hh[4];
#pragma unroll
    for (int k = 0; k < 4; k++) hh[k] = __bfloat162float(__float2bfloat16(vv[k]));
    *(uint32_t*)&g_Xhi[i]     = pack2bf(hh[0], hh[1]);
    *(uint32_t*)&g_Xhi[i + 2] = pack2bf(hh[2], hh[3]);
    *(uint32_t*)&g_Xlo[i]     = pack2bf(vv[0] - hh[0], vv[1] - hh[1]);
    *(uint32_t*)&g_Xlo[i + 2] = pack2bf(vv[2] - hh[2], vv[3] - hh[3]);
}

// ---------------- duration cumsum + searchsorted ----------------
__global__ void duration_idx_kernel(const int* __restrict__ Dgt) {
    __shared__ int cs[512];
    int b = blockIdx.x, tid = threadIdx.x;
    int v = Dgt[b * 512 + tid];
    cs[tid] = v > 0 ? v : 0;
    __syncthreads();
    for (int off = 1; off < 512; off <<= 1) {
        int add = (tid >= off) ? cs[tid - off] : 0;
        __syncthreads();
        cs[tid] += add;
        __syncthreads();
    }
    int total = cs[511];
    int Tmax  = total < MAXF ? total : MAXF;
    for (int t = tid; t < MAXF; t += 512) {
        int r;
        if (t >= Tmax) {
            r = -1;
        } else {
            int lo = 0, hi = 511;
            while (lo < hi) {
                int mid = (lo + hi) >> 1;
                if (cs[mid] > t) hi = mid; else lo = mid + 1;
            }
            r = lo;
        }
        g_idx[b * MAXF + t] = r;
    }
}

// ---------------- gather H_exp (split to g_X) + fused variance adapt ----------------
__global__ void gather_adapt_kernel(const float* __restrict__ H,
                                    const float* __restrict__ P,
                                    const float* __restrict__ E,
                                    const float* __restrict__ pw,
                                    const float* __restrict__ pb,
                                    const float* __restrict__ ew,
                                    const float* __restrict__ eb,
                                    float* __restrict__ outH) {
    int bt  = blockIdx.x;
    int b   = bt >> 11;
    int idx = g_idx[bt];
    int d   = threadIdx.x * 4;
    float4 h = make_float4(0.f, 0.f, 0.f, 0.f);
    if (idx >= 0) h = *(const float4*)&H[((long)(b * 512 + idx)) * 512 + d];

    long xo = (long)bt * 512 + d;
    float vv[4] = {h.x, h.y, h.z, h.w};
    float hh[4];
#pragma unroll
    for (int k = 0; k < 4; k++) hh[k] = __bfloat162float(__float2bfloat16(vv[k]));
    *(uint32_t*)&g_Xhi[xo]     = pack2bf(hh[0], hh[1]);
    *(uint32_t*)&g_Xhi[xo + 2] = pack2bf(hh[2], hh[3]);
    *(uint32_t*)&g_Xlo[xo]     = pack2bf(vv[0] - hh[0], vv[1] - hh[1]);
    *(uint32_t*)&g_Xlo[xo + 2] = pack2bf(vv[2] - hh[2], vv[3] - hh[3]);

    float p = P[bt], e = E[bt];
    float4 pw4 = *(const float4*)&pw[d];
    float4 pb4 = *(const float4*)&pb[d];
    float4 ew4 = *(const float4*)&ew[d];
    float4 eb4 = *(const float4*)&eb[d];
    float4 o;
    o.x = h.x + p * pw4.x + pb4.x + e * ew4.x + eb4.x;
    o.y = h.y + p * pw4.y + pb4.y + e * ew4.y + eb4.y;
    o.z = h.z + p * pw4.z + pb4.z + e * ew4.z + eb4.z;
    o.w = h.w + p * pw4.w + pb4.w + e * ew4.w + eb4.w;
    *(float4*)&outH[xo] = o;
}

// ---------------- tensor-core conv1d via mma.sync, 3xBF16 compensated ----------------
// CTA: 128 rows x 128 filters, 512 threads (16 warps, warp tile 32x32).
// A staged ONCE per 64-ch chunk (130 rows incl halo), taps via ldmatrix row offset.
// B triple-buffered ring (slot == tap), A double-buffered. One barrier / iteration.
// Smem layout (dynamic): A0hi A0lo A1hi A1lo (4 x 16640) | B0h B0l B1h B1l B2h B2l (6 x 16384)
#define A_BUF   33280      // hi+lo per A buffer
#define A_HALF  16640
#define B_BASE  66560
#define B_BUF   32768
#define B_HALF  16384
#define DSM_TOT (66560 + 98304)   // 164864

template <int FUSED>
__global__ __launch_bounds__(512, 1)
void conv_mma_kernel(int xsel, int conv, int S,
                     const float* __restrict__ bias, const float* __restrict__ wl) {
    extern __shared__ char sm[];
    const uint32_t sb = smem_to_u32(sm);
    __shared__ float s_bias[128];
    __shared__ float s_wl[128];
    __shared__ float s_part[128][4];

    const int tid  = threadIdx.x;
    const int lane = tid & 31;
    const int wid  = tid >> 5;
    const int warpM = wid & 3, warpN = wid >> 2;
    const int rowW = warpM * 32, colW = warpN * 32;

    const int rowBase = blockIdx.y * 128;
    const int fBase   = blockIdx.x * 128;
    const int bb = rowBase / S;
    const int s0 = rowBase - bb * S;

    const __nv_bfloat16* Xhi = (xsel == 0 ? g_Xhi : g_Yhi) + (long)bb * S * 512;
    const __nv_bfloat16* Xlo = (xsel == 0 ? g_Xlo : g_Ylo) + (long)bb * S * 512;
    const __nv_bfloat16* WhC = g_Whi + ((long)(conv * 3) * 512 + fBase) * 512;
    const __nv_bfloat16* WlC = g_Wlo + ((long)(conv * 3) * 512 + fBase) * 512;

    if (tid < 128) {
        s_bias[tid] = bias[fBase + tid];
        if (FUSED) s_wl[tid] = wl[fBase + tid];
    }

    // ---- stage A chunk c: 130 rows x 64 ch (hi+lo) ----
    auto stageA = [&](int c) {
        const int c0 = c << 6;
        const uint32_t abuf = sb + (c & 1) * A_BUF;
#pragma unroll
        for (int q = 0; q < 3; q++) {
            int idx = tid + q * 512;
            if (idx < 1040) {                 // 130 rows x 8 segs
                int r = idx >> 3, c16 = idx & 7;
                int s = s0 - 1 + r;
                bool p = (s >= 0 && s < S);
                int sc = p ? s : 0;
                long off = (long)sc * 512 + c0 + c16 * 8;
                uint32_t dsw = (uint32_t)(r * 128 + ((c16 ^ (r & 7)) << 4));
                cpasync16(abuf + dsw,          Xhi + off, p);
                cpasync16(abuf + A_HALF + dsw, Xlo + off, p);
            }
        }
    };
    // ---- stage B for iteration it (chunk it/3, tap it%3) into ring slot it%3 ----
    auto stageB = [&](int it) {
        const int tap = it % 3;
        const int c0  = (it / 3) << 6;
        const uint32_t bbuf = sb + B_BASE + tap * B_BUF;
        const __nv_bfloat16* Wh = WhC + (long)tap * 512 * 512 + c0;
        const __nv_bfloat16* Wl = WlC + (long)tap * 512 * 512 + c0;
#pragma unroll
        for (int q = 0; q < 2; q++) {
            int idx = tid + q * 512;          // 0..1023: 128 filters x 8 segs
            int r = idx >> 3, c16 = idx & 7;
            long off = (long)r * 512 + c16 * 8;
            uint32_t dsw = (uint32_t)(r * 128 + ((c16 ^ (r & 7)) << 4));
            cpasync16(bbuf + dsw,          Wh + off, true);
            cpasync16(bbuf + B_HALF + dsw, Wl + off, true);
        }
    };

    // ---- per-lane ldmatrix bases ----
    const int q = lane >> 3;
    int am[2], an[2];
#pragma unroll
    for (int mt = 0; mt < 2; mt++) am[mt] = rowW + mt * 16 + ((q & 1) << 3) + (lane & 7);
#pragma unroll
    for (int np = 0; np < 2; np++) an[np] = colW + np * 16 + ((q >> 1) << 3) + (lane & 7);
    const int ac16b = q >> 1;
    const int bc16b = q & 1;

    float acc[2][4][4];
#pragma unroll
    for (int mt = 0; mt < 2; mt++)
#pragma unroll
        for (int nt = 0; nt < 4; nt++)
#pragma unroll
            for (int v = 0; v < 4; v++) acc[mt][nt][v] = 0.f;

    stageA(0); stageB(0); CP_COMMIT();        // group 0
    stageB(1);            CP_COMMIT();        // group 1

    for (int it = 0; it < 24; it++) {
        CP_WAIT1();                            // group 'it' complete
        __syncthreads();
        const int tap = it % 3;
        const uint32_t aH = sb + ((it / 3) & 1) * A_BUF;
        const uint32_t aL = aH + A_HALF;
        const uint32_t bH = sb + B_BASE + tap * B_BUF;
        const uint32_t bL = bH + B_HALF;

#pragma unroll
        for (int ks = 0; ks < 4; ks++) {
            const int ks2 = ks * 2;
            uint32_t ah[2][4], al[2][4];
#pragma unroll
            for (int mt = 0; mt < 2; mt++) {
                const int pr = am[mt] + tap;
                uint32_t off = (uint32_t)(pr * 128 + (((ks2 + ac16b) ^ (pr & 7)) << 4));
                ldmx4(ah[mt], aH + off);
                ldmx4(al[mt], aL + off);
            }
            uint32_t bh[4][2], bl[4][2];
#pragma unroll
            for (int np = 0; np < 2; np++) {
                uint32_t off = (uint32_t)(an[np] * 128 + (((ks2 + bc16b) ^ (an[np] & 7)) << 4));
                uint32_t t[4];
                ldmx4(t, bH + off);
                bh[2 * np][0] = t[0]; bh[2 * np][1] = t[1];
                bh[2 * np + 1][0] = t[2]; bh[2 * np + 1][1] = t[3];
                ldmx4(t, bL + off);
                bl[2 * np][0] = t[0]; bl[2 * np][1] = t[1];
                bl[2 * np + 1][0] = t[2]; bl[2 * np + 1][1] = t[3];
            }
#pragma unroll
            for (int mt = 0; mt < 2; mt++)
#pragma unroll
                for (int nt = 0; nt < 4; nt++) mma16816(acc[mt][nt], ah[mt], bh[nt]);
#pragma unroll
            for (int mt = 0; mt < 2; mt++)
#pragma unroll
                for (int nt = 0; nt < 4; nt++) mma16816(acc[mt][nt], ah[mt], bl[nt]);
#pragma unroll
            for (int mt = 0; mt < 2; mt++)
#pragma unroll
                for (int nt = 0; nt < 4; nt++) mma16816(acc[mt][nt], al[mt], bh[nt]);
        }

        const int nx = it + 2;
        if (nx < 24) {
            if (nx % 3 == 0) stageA(nx / 3);
            stageB(nx);
        }
        CP_COMMIT();
    }

    // ---------------- epilogue ----------------
    const int tq = lane >> 2;
    const int tr = lane & 3;
    if (FUSED == 0) {
#pragma unroll
        for (int mt = 0; mt < 2; mt++) {
            const long r0 = rowBase + rowW + mt * 16 + tq;
#pragma unroll
            for (int nt = 0; nt < 4; nt++) {
                const int cl = colW + nt * 8 + 2 * tr;
                const float b0 = s_bias[cl], b1 = s_bias[cl + 1];
#pragma unroll
                for (int h = 0; h < 2; h++) {
                    const long row = r0 + h * 8;
                    float v0 = fmaxf(acc[mt][nt][2 * h]     + b0, 0.f);
                    float v1 = fmaxf(acc[mt][nt][2 * h + 1] + b1, 0.f);
                    float h0 = __bfloat162float(__float2bfloat16(v0));
                    float h1 = __bfloat162float(__float2bfloat16(v1));
                    long o = row * 512 + fBase + cl;
                    *(uint32_t*)&g_Yhi[o] = pack2bf(h0, h1);
                    *(uint32_t*)&g_Ylo[o] = pack2bf(v0 - h0, v1 - h1);
                }
            }
        }
    } else {
#pragma unroll
        for (int mt = 0; mt < 2; mt++) {
            float sum0 = 0.f, sum1 = 0.f;
#pragma unroll
            for (int nt = 0; nt < 4; nt++) {
                const int cl = colW + nt * 8 + 2 * tr;
                const float b0 = s_bias[cl], b1 = s_bias[cl + 1];
                const float w0 = s_wl[cl], w1 = s_wl[cl + 1];
                sum0 += fmaxf(acc[mt][nt][0] + b0, 0.f) * w0
                      + fmaxf(acc[mt][nt][1] + b1, 0.f) * w1;
                sum1 += fmaxf(acc[mt][nt][2] + b0, 0.f) * w0
                      + fmaxf(acc[mt][nt][3] + b1, 0.f) * w1;
            }
            sum0 += __shfl_xor_sync(0xFFFFFFFF, sum0, 1);
            sum0 += __shfl_xor_sync(0xFFFFFFFF, sum0, 2);
            sum1 += __shfl_xor_sync(0xFFFFFFFF, sum1, 1);
            sum1 += __shfl_xor_sync(0xFFFFFFFF, sum1, 2);
            if (tr == 0) {
                s_part[rowW + mt * 16 + tq][warpN]     = sum0;
                s_part[rowW + mt * 16 + tq + 8][warpN] = sum1;
            }
        }
        __syncthreads();
        if (tid < 128)
            g_part[(long)(rowBase + tid) * 4 + blockIdx.x] =
                (s_part[tid][0] + s_part[tid][1]) + (s_part[tid][2] + s_part[tid][3]);
    }
}

// ---------------- final pred reduce ----------------
__global__ void pred_reduce_kernel(const float* __restrict__ bl,
                                   float* __restrict__ out, int rows) {
    int i = blockIdx.x * 256 + threadIdx.x;
    if (i < rows)
        out[i] = bl[0] + g_part[(long)i * 4 + 0] + g_part[(long)i * 4 + 1] +
                 g_part[(long)i * 4 + 2] + g_part[(long)i * 4 + 3];
}

// ---------------- launch ----------------
extern "C" void kernel_launch(void* const* d_in, const int* in_sizes, int n_in,
                              void* d_out, int out_size) {
    const float* H     = (const float*)d_in[0];
    const int*   Dgt   = (const int*)  d_in[1];
    const float* Pgt   = (const float*)d_in[2];
    const float* Egt   = (const float*)d_in[3];
    const float* dp_w1 = (const float*)d_in[4];
    const float* dp_b1 = (const float*)d_in[5];
    const float* dp_w2 = (const float*)d_in[6];
    const float* dp_b2 = (const float*)d_in[7];
    const float* dp_wl = (const float*)d_in[8];
    const float* dp_bl = (const float*)d_in[9];
    const float* pp_w1 = (const float*)d_in[10];
    const float* pp_b1 = (const float*)d_in[11];
    const float* pp_w2 = (const float*)d_in[12];
    const float* pp_b2 = (const float*)d_in[13];
    const float* pp_wl = (const float*)d_in[14];
    const float* pp_bl = (const float*)d_in[15];
    const float* ep_w1 = (const float*)d_in[16];
    const float* ep_b1 = (const float*)d_in[17];
    const float* ep_w2 = (const float*)d_in[18];
    const float* ep_b2 = (const float*)d_in[19];
    const float* ep_wl = (const float*)d_in[20];
    const float* ep_bl = (const float*)d_in[21];
    const float* pw    = (const float*)d_in[22];
    const float* pb    = (const float*)d_in[23];
    const float* ew    = (const float*)d_in[24];
    const float* eb    = (const float*)d_in[25];

    float* out  = (float*)d_out;
    float* outH = out;                                   // (16,2048,512)
    float* outD = out + (long)NB * MAXF * DMODEL;        // (16,512)
    float* outP = outD + NB * SEQ;                       // (16,2048)
    float* outE = outP + NB * MAXF;                      // (16,2048)

    cudaFuncSetAttribute(conv_mma_kernel<0>, cudaFuncAttributeMaxDynamicSharedMemorySize, DSM_TOT);
    cudaFuncSetAttribute(conv_mma_kernel<1>, cudaFuncAttributeMaxDynamicSharedMemorySize, DSM_TOT);

    wsplit_kernel<<<1536, 512>>>(dp_w1, 0);
    wsplit_kernel<<<1536, 512>>>(dp_w2, 1);
    wsplit_kernel<<<1536, 512>>>(pp_w1, 2);
    wsplit_kernel<<<1536, 512>>>(pp_w2, 3);
    wsplit_kernel<<<1536, 512>>>(ep_w1, 4);
    wsplit_kernel<<<1536, 512>>>(ep_w2, 5);

    duration_idx_kernel<<<NB, 512>>>(Dgt);

    // ---- duration predictor (input: split H; S=512) ----
    hsplit_kernel<<<NB * SEQ, 128>>>(H);
    conv_mma_kernel<0><<<dim3(4, 64), 512, DSM_TOT>>>(0, 0, SEQ, dp_b1, nullptr);
    conv_mma_kernel<1><<<dim3(4, 64), 512, DSM_TOT>>>(1, 1, SEQ, dp_b2, dp_wl);
    pred_reduce_kernel<<<32, 256>>>(dp_bl, outD, NB * SEQ);

    // ---- expand + adapt (overwrites g_X with split Hexp; writes outH fp32) ----
    gather_adapt_kernel<<<NB * MAXF, 128>>>(H, Pgt, Egt, pw, pb, ew, eb, outH);

    // ---- pitch predictor (input: split Hexp; S=2048) ----
    conv_mma_kernel<0><<<dim3(4, 256), 512, DSM_TOT>>>(0, 2, MAXF, pp_b1, nullptr);
    conv_mma_kernel<1><<<dim3(4, 256), 512, DSM_TOT>>>(1, 3, MAXF, pp_b2, pp_wl);
    pred_reduce_kernel<<<128, 256>>>(pp_bl, outP, NB * MAXF);

    // ---- energy predictor (input: split Hexp, still in g_X; S=2048) ----
    conv_mma_kernel<0><<<dim3(4, 256), 512, DSM_TOT>>>(0, 4, MAXF, ep_b1, nullptr);
    conv_mma_kernel<1><<<dim3(4, 256), 512, DSM_TOT>>>(1, 5, MAXF, ep_b2, ep_wl);
    pred_reduce_kernel<<<128, 256>>>(ep_bl, outE, NB * MAXF);
}